// round 10
// baseline (speedup 1.0000x reference)
#include <cuda_runtime.h>
#include <math.h>

// BaseRoIHead multi-level RoIAlign (torchvision-style, aligned=False)
// B=2, R=512, C=256, out 7x7, sampling_ratio=2, levels p2..p6 (strides 4..64).
//
//  - one CTA per (roi, out-row): grid (1024, 7), 128 threads = 1 float2 group
//  - branchless: validity + 0.25 mean folded into precomputed shared weights,
//    all 16 float2 gathers per bin unconditional (clamped indices in-bounds)
//  - per-bin x data packed (int4 offsets + float4 weights) -> 2 LDS.128/bin
//  - float2 halves per-thread load-data registers -> 12 CTAs/SM (75% occ)

#define OUT_HW 7
#define CCH 256
#define NT  128            // threads = float2 channel groups

__device__ __forceinline__ float2 f2fma(float s, float2 v, float2 a) {
    a.x = fmaf(s, v.x, a.x); a.y = fmaf(s, v.y, a.y);
    return a;
}

__global__ __launch_bounds__(NT, 12) void roialign_fpn_kernel(
    const float* __restrict__ p2, const float* __restrict__ p3,
    const float* __restrict__ p4, const float* __restrict__ p5,
    const float* __restrict__ p6, const float* __restrict__ proposals,
    float* __restrict__ out)
{
    const int roi = blockIdx.x;          // b * 512 + r
    const int oh  = blockIdx.y;          // output row 0..6
    const int b   = roi >> 9;
    const int tx  = threadIdx.x;         // 0..127 float2 channel group

    __shared__ int4   s_xo[OUT_HW];      // per-bin x offsets (oa0,ob0,oa1,ob1)
    __shared__ float4 s_xw[OUT_HW];      // per-bin x weights (hx0,lx0,hx1,lx1)
    __shared__ int    s_rowoff[4];       // ya0,yb0,ya1,yb1 element offsets
    __shared__ float  s_wy[4];           // masked y weights * 0.25
    __shared__ const float* s_feat;

    if (tx < 32) {
        // uniform box/level scalars computed redundantly by every lane
        const float* box = proposals + (size_t)roi * 4;
        float bx1 = box[0], by1 = box[1], bx2 = box[2], by2 = box[3];

        float w = fmaxf(bx2 - bx1, 1.0f);
        float h = fmaxf(by2 - by1, 1.0f);
        float lvlf = floorf(4.0f + log2f(sqrtf(w * h) / 224.0f));
        int lvl = (int)fminf(fmaxf(lvlf, 2.0f), 6.0f);   // 2..6

        int H = 1024 >> lvl;
        float Hf = (float)H;
        float scale = 1.0f / (float)(1 << lvl);

        float x1s = bx1 * scale, y1s = by1 * scale;
        float bin_w = fmaxf(bx2 * scale - x1s, 1.0f) / (float)OUT_HW;
        float bin_h = fmaxf(by2 * scale - y1s, 1.0f) / (float)OUT_HW;

        if (tx < OUT_HW) {
            // lanes 0..6: both x-samples of bin `tx`, packed
            const int ow = tx;
            int   oa[2], ob[2];
            float hx[2], lx[2];
            #pragma unroll
            for (int k = 0; k < 2; k++) {
                const int j = ow * 2 + k;
                float pos = (float)(j >> 1) + ((float)(j & 1) + 0.5f) * 0.5f;
                float X = x1s + pos * bin_w;
                bool ok = (X >= -1.0f) && (X <= Hf);
                float x = fminf(fmaxf(X, 0.0f), Hf - 1.0f);
                float x0 = floorf(x);
                int xa = (int)x0;
                int xb = min(xa + 1, H - 1);
                float l = x - x0;
                oa[k] = xa * CCH;
                ob[k] = xb * CCH;
                hx[k] = ok ? (1.0f - l) : 0.0f;
                lx[k] = ok ? l : 0.0f;
            }
            s_xo[ow] = make_int4(oa[0], ob[0], oa[1], ob[1]);
            s_xw[ow] = make_float4(hx[0], lx[0], hx[1], lx[1]);
        } else if (tx == 16) {
            // lane 16: the two y-samples of this output row
            #pragma unroll
            for (int k = 0; k < 2; k++) {
                const int iy = oh * 2 + k;
                float pos = (float)(iy >> 1) + ((float)(iy & 1) + 0.5f) * 0.5f;
                float Y = y1s + pos * bin_h;
                bool ok = (Y >= -1.0f) && (Y <= Hf);
                float y = fminf(fmaxf(Y, 0.0f), Hf - 1.0f);
                float y0 = floorf(y);
                int ya = (int)y0;
                int yb = min(ya + 1, H - 1);
                float ly = y - y0;
                s_rowoff[2 * k]     = ya * H * CCH;
                s_rowoff[2 * k + 1] = yb * H * CCH;
                s_wy[2 * k]     = ok ? (1.0f - ly) * 0.25f : 0.0f;
                s_wy[2 * k + 1] = ok ? ly * 0.25f : 0.0f;
            }
        } else if (tx == 31) {
            const float* feats[5] = {p2, p3, p4, p5, p6};
            s_feat = feats[lvl - 2] + (size_t)b * H * H * CCH;
        }
    }
    __syncthreads();

    const int cb = tx * 2;               // channel base (float2)
    const float* base = s_feat + cb;
    const float* r0 = base + s_rowoff[0];
    const float* r1 = base + s_rowoff[1];
    const float* r2 = base + s_rowoff[2];
    const float* r3 = base + s_rowoff[3];
    const float wy0 = s_wy[0], wy1 = s_wy[1], wy2 = s_wy[2], wy3 = s_wy[3];

    float* orow = out + ((size_t)roi * (OUT_HW * OUT_HW) + oh * OUT_HW) * CCH + cb;

    #pragma unroll
    for (int ow = 0; ow < OUT_HW; ow++) {
        const int4   xo = s_xo[ow];
        const float4 xw = s_xw[ow];

        // 16 unconditional coalesced gathers (128 lanes x 8B = 1KB each)
        float2 vA0a0 = *(const float2*)(r0 + xo.x);
        float2 vA0b0 = *(const float2*)(r0 + xo.y);
        float2 vA0a1 = *(const float2*)(r0 + xo.z);
        float2 vA0b1 = *(const float2*)(r0 + xo.w);
        float2 vB0a0 = *(const float2*)(r1 + xo.x);
        float2 vB0b0 = *(const float2*)(r1 + xo.y);
        float2 vB0a1 = *(const float2*)(r1 + xo.z);
        float2 vB0b1 = *(const float2*)(r1 + xo.w);
        float2 vA1a0 = *(const float2*)(r2 + xo.x);
        float2 vA1b0 = *(const float2*)(r2 + xo.y);
        float2 vA1a1 = *(const float2*)(r2 + xo.z);
        float2 vA1b1 = *(const float2*)(r2 + xo.w);
        float2 vB1a0 = *(const float2*)(r3 + xo.x);
        float2 vB1b0 = *(const float2*)(r3 + xo.y);
        float2 vB1a1 = *(const float2*)(r3 + xo.z);
        float2 vB1b1 = *(const float2*)(r3 + xo.w);

        float2 acc = make_float2(0.f, 0.f);
        acc = f2fma(wy0 * xw.x, vA0a0, acc);
        acc = f2fma(wy0 * xw.y, vA0b0, acc);
        acc = f2fma(wy0 * xw.z, vA0a1, acc);
        acc = f2fma(wy0 * xw.w, vA0b1, acc);
        acc = f2fma(wy1 * xw.x, vB0a0, acc);
        acc = f2fma(wy1 * xw.y, vB0b0, acc);
        acc = f2fma(wy1 * xw.z, vB0a1, acc);
        acc = f2fma(wy1 * xw.w, vB0b1, acc);
        acc = f2fma(wy2 * xw.x, vA1a0, acc);
        acc = f2fma(wy2 * xw.y, vA1b0, acc);
        acc = f2fma(wy2 * xw.z, vA1a1, acc);
        acc = f2fma(wy2 * xw.w, vA1b1, acc);
        acc = f2fma(wy3 * xw.x, vB1a0, acc);
        acc = f2fma(wy3 * xw.y, vB1b0, acc);
        acc = f2fma(wy3 * xw.z, vB1a1, acc);
        acc = f2fma(wy3 * xw.w, vB1b1, acc);

        *(float2*)(orow + ow * CCH) = acc;
    }
}

extern "C" void kernel_launch(void* const* d_in, const int* in_sizes, int n_in,
                              void* d_out, int out_size) {
    // Identify inputs by element count (all distinct):
    // p2=33554432, p3=8388608, p4=2097152, p5=524288, p6=131072, proposals=4096
    const float* ptr[6] = {nullptr, nullptr, nullptr, nullptr, nullptr, nullptr};
    int num_rois = 1024;
    for (int i = 0; i < n_in && i < 6; i++) {
        switch (in_sizes[i]) {
            case 33554432: ptr[0] = (const float*)d_in[i]; break;  // p2
            case 8388608:  ptr[1] = (const float*)d_in[i]; break;  // p3
            case 2097152:  ptr[2] = (const float*)d_in[i]; break;  // p4
            case 524288:   ptr[3] = (const float*)d_in[i]; break;  // p5
            case 131072:   ptr[4] = (const float*)d_in[i]; break;  // p6
            default:       ptr[5] = (const float*)d_in[i];
                           num_rois = in_sizes[i] / 4;     break;  // proposals
        }
    }

    dim3 grid(num_rois, OUT_HW, 1);
    roialign_fpn_kernel<<<grid, NT>>>(ptr[0], ptr[1], ptr[2], ptr[3],
                                      ptr[4], ptr[5], (float*)d_out);
}